// round 1
// baseline (speedup 1.0000x reference)
#include <cuda_runtime.h>
#include <cuda_bf16.h>

// PointPillarsScatter: out[b, c, y, x] = feat[n, c] where coords[n] = (b, _, y, x), else 0.
// Strategy: inverse-index gather. Build g_map[b*HW + y*NX + x] = n (or -1),
// then write the 219MB output exactly once with coalesced float4 stores.

#define NYd 496
#define NXd 432
#define Cd  64
#define Bd  4
#define HWd (NYd * NXd)          // 214272
#define MAPN (Bd * HWd)          // 857088 ints, 3.4 MB scratch

__device__ int g_map[MAPN];

// ---- Kernel 1: init map to -1 (int4 vectorized; MAPN % 4 == 0) ----
__global__ void init_map_kernel() {
    int i = blockIdx.x * blockDim.x + threadIdx.x;
    if (i < MAPN / 4) {
        ((int4*)g_map)[i] = make_int4(-1, -1, -1, -1);
    }
}

// ---- Kernel 2: scatter pillar index into map ----
__global__ void scatter_map_kernel(const int* __restrict__ coords, int n_total) {
    int n = blockIdx.x * blockDim.x + threadIdx.x;
    if (n >= n_total) return;
    int4 cc = ((const int4*)coords)[n];   // (b, z, y, x)
    g_map[(cc.x * NYd + cc.z) * NXd + cc.w] = n;
}

// ---- Kernel 3: gather-write output, coalesced float4 stores ----
// One thread per (b, y, x/4). Loops over all C channels so the map read
// (int4, coalesced) is amortized 64x. Feature gathers hit L2 (feat = 12MB).
__global__ void __launch_bounds__(128) write_out_kernel(
        const float* __restrict__ feat, float* __restrict__ out) {
    const int XV = NXd / 4;  // 108
    int tid = blockIdx.x * blockDim.x + threadIdx.x;
    if (tid >= Bd * NYd * XV) return;

    int x4 = tid % XV;
    int t  = tid / XV;
    int y  = t % NYd;
    int b  = t / NYd;

    int4 m = *(const int4*)&g_map[(b * NYd + y) * NXd + x4 * 4];

    // out offset for channel c: ((b*C + c)*NY + y)*NX + x
    float* outp = out + ((b * Cd) * NYd + y) * NXd + x4 * 4;

    const float* f0 = feat + (long)m.x * Cd;
    const float* f1 = feat + (long)m.y * Cd;
    const float* f2 = feat + (long)m.z * Cd;
    const float* f3 = feat + (long)m.w * Cd;

    #pragma unroll 8
    for (int c = 0; c < Cd; c++) {
        float4 v;
        v.x = (m.x >= 0) ? __ldg(f0 + c) : 0.0f;
        v.y = (m.y >= 0) ? __ldg(f1 + c) : 0.0f;
        v.z = (m.z >= 0) ? __ldg(f2 + c) : 0.0f;
        v.w = (m.w >= 0) ? __ldg(f3 + c) : 0.0f;
        *(float4*)(outp + c * HWd) = v;
    }
}

extern "C" void kernel_launch(void* const* d_in, const int* in_sizes, int n_in,
                              void* d_out, int out_size) {
    const float* feat   = (const float*)d_in[0];
    const int*   coords = (const int*)d_in[1];
    int n_total = in_sizes[1] / 4;

    // 1) map := -1
    {
        int n4 = MAPN / 4;
        init_map_kernel<<<(n4 + 255) / 256, 256>>>();
    }
    // 2) map[idx] = n
    scatter_map_kernel<<<(n_total + 255) / 256, 256>>>(coords, n_total);
    // 3) gather-write full output
    {
        int nthreads = Bd * NYd * (NXd / 4);   // 214272
        write_out_kernel<<<(nthreads + 127) / 128, 128>>>(feat, (float*)d_out);
    }
}

// round 2
// speedup vs baseline: 1.2411x; 1.2411x over previous
#include <cuda_runtime.h>
#include <cuda_bf16.h>

// PointPillarsScatter: out[b, c, y, x] = feat[n, c] where coords[n] = (b, _, y, x), else 0.
// Strategy: inverse-index gather. memset g_map to -1, scatter pillar index n into
// g_map[b,y,x], then write the 219MB output exactly once with coalesced float4
// streaming stores. Channel loop split across 2 threads for store MLP.

#define NYd 496
#define NXd 432
#define Cd  64
#define Bd  4
#define HWd (NYd * NXd)          // 214272
#define MAPN (Bd * HWd)          // 857088 ints, 3.4 MB scratch

__device__ int g_map[MAPN];

// ---- Kernel 1: scatter pillar index into map (map pre-set to -1 via memset) ----
__global__ void scatter_map_kernel(const int* __restrict__ coords, int n_total) {
    int n = blockIdx.x * blockDim.x + threadIdx.x;
    if (n >= n_total) return;
    int4 cc = ((const int4*)coords)[n];   // (b, z, y, x)
    g_map[(cc.x * NYd + cc.z) * NXd + cc.w] = n;
}

// ---- Kernel 2: gather-write output, coalesced float4 streaming stores ----
// One thread per (half, b, y, x/4); each thread covers 32 channels so the map
// read (int4, coalesced) is amortized 32x. 'half' is the outermost (slow)
// dimension so warp lanes stay consecutive in x -> 512B contiguous stores.
__global__ void __launch_bounds__(256) write_out_kernel(
        const float* __restrict__ feat, float* __restrict__ out) {
    const int XV = NXd / 4;  // 108
    int tid = blockIdx.x * blockDim.x + threadIdx.x;
    if (tid >= 2 * Bd * NYd * XV) return;

    int t    = tid;
    int x4   = t % XV;  t /= XV;
    int y    = t % NYd; t /= NYd;
    int b    = t % Bd;
    int half = t / Bd;            // 0 or 1
    int c0   = half * (Cd / 2);   // 0 or 32

    int4 m = *(const int4*)&g_map[(b * NYd + y) * NXd + x4 * 4];

    // out offset for channel c: ((b*C + c)*NY + y)*NX + x
    float* outp = out + ((b * Cd + c0) * NYd + y) * NXd + x4 * 4;

    const float* f0 = feat + (long)m.x * Cd + c0;
    const float* f1 = feat + (long)m.y * Cd + c0;
    const float* f2 = feat + (long)m.z * Cd + c0;
    const float* f3 = feat + (long)m.w * Cd + c0;

    #pragma unroll 16
    for (int c = 0; c < Cd / 2; c++) {
        float4 v;
        v.x = (m.x >= 0) ? __ldg(f0 + c) : 0.0f;
        v.y = (m.y >= 0) ? __ldg(f1 + c) : 0.0f;
        v.z = (m.z >= 0) ? __ldg(f2 + c) : 0.0f;
        v.w = (m.w >= 0) ? __ldg(f3 + c) : 0.0f;
        __stcs((float4*)(outp + c * HWd), v);
    }
}

extern "C" void kernel_launch(void* const* d_in, const int* in_sizes, int n_in,
                              void* d_out, int out_size) {
    const float* feat   = (const float*)d_in[0];
    const int*   coords = (const int*)d_in[1];
    int n_total = in_sizes[1] / 4;

    // 1) map := -1 (0xFF bytes) — async memset node, graph-capturable, no alloc
    void* map_ptr = nullptr;
    cudaGetSymbolAddress(&map_ptr, g_map);
    cudaMemsetAsync(map_ptr, 0xFF, (size_t)MAPN * sizeof(int), 0);

    // 2) map[idx] = n
    scatter_map_kernel<<<(n_total + 255) / 256, 256>>>(coords, n_total);

    // 3) gather-write full output (2 threads per cell-quad: 32 channels each)
    {
        int nthreads = 2 * Bd * NYd * (NXd / 4);   // 428544
        write_out_kernel<<<(nthreads + 255) / 256, 256>>>(feat, (float*)d_out);
    }
}